// round 5
// baseline (speedup 1.0000x reference)
#include <cuda_runtime.h>
#include <cstdint>

typedef unsigned long long ULL;

// Problem constants
constexpr int Bz = 16, C = 64, H = 64, W = 64;
constexpr int N  = Bz * H * W;     // 65536 rows
constexpr int K  = 1024;           // codes
constexpr int HW = H * W;          // 4096
constexpr int CHW = C * HW;        // 262144

// argmin tiling: 128 rows per CTA x 8 chunks of 128 codes
constexpr int TM  = 128;
constexpr int CH  = 128;
constexpr int NCH = K / CH;        // 8

// smem layout (bytes). float2 pitch 66 per 64-k row (conflict-free frags).
constexpr int P2       = 66;
constexpr int A2_BYTES = TM * P2 * 8;          // 67584
constexpr int B2_OFF   = A2_BYTES;             // two buffers follow
constexpr int B2_BYTES = CH * P2 * 8;          // 67584
constexpr int EN_OFF   = B2_OFF + 2 * B2_BYTES;   // 202752
constexpr int ZN_OFF   = EN_OFF + 4096;           // 206848
constexpr int RED_OFF  = ZN_OFF + 512;            // 207360: ULL red[2][2][128]
constexpr int SMEM_BYTES = RED_OFF + 8192;        // 215552

// tie-repair window: 8 ulp at magnitude ~64 (decision band is <= 2 ulp)
constexpr float EPS_TIE = 6.104e-5f;

// Device scratch (no allocations allowed)
__device__ int    g_idx[N];
__device__ float  g_enorm[K];
__device__ float2 g_emb2[K * C];   // (hi,lo) split of emb, [code][k]
__device__ double g_partials[256];

__device__ __forceinline__ uint32_t smem_u32(const void* p) {
    uint32_t a;
    asm("{ .reg .u64 t; cvta.to.shared.u64 t, %1; cvt.u32.u64 %0, t; }" : "=r"(a) : "l"(p));
    return a;
}
__device__ __forceinline__ void cp_async16(uint32_t dst, const void* src) {
    asm volatile("cp.async.cg.shared.global [%0], [%1], 16;\n" :: "r"(dst), "l"(src));
}
__device__ __forceinline__ void mma8(float* d,
                                     uint32_t a0, uint32_t a1, uint32_t a2, uint32_t a3,
                                     uint32_t b0, uint32_t b1) {
    asm volatile("mma.sync.aligned.m16n8k8.row.col.f32.tf32.tf32.f32 "
                 "{%0,%1,%2,%3}, {%4,%5,%6,%7}, {%8,%9}, {%0,%1,%2,%3};"
                 : "+f"(d[0]), "+f"(d[1]), "+f"(d[2]), "+f"(d[3])
                 : "r"(a0), "r"(a1), "r"(a2), "r"(a3), "r"(b0), "r"(b1));
}
__device__ __forceinline__ uint32_t fu(float x) { return __float_as_uint(x); }
__device__ __forceinline__ ULL umin(ULL a, ULL b) { return a < b ? a : b; }
__device__ __forceinline__ ULL umax(ULL a, ULL b) { return a > b ? a : b; }

// ---------------------------------------------------------------------------
// Kernel 0: per-code ||e||^2 (reference rounding) + tf32 hi/lo split of emb.
// ---------------------------------------------------------------------------
__global__ void prep_kernel(const float* __restrict__ emb) {
    int code = blockIdx.x * blockDim.x + threadIdx.x;   // 0..1023
    if (code < K) {
        const float* e = emb + code * C;
        float2* o = g_emb2 + code * C;
        float acc = 0.f;
        #pragma unroll
        for (int c = 0; c < C; c++) {
            float v = e[c];
            acc = __fadd_rn(acc, __fmul_rn(v, v));
            float hi = __uint_as_float(__float_as_uint(v) & 0xFFFFE000u);
            float lo = __fadd_rn(v, -hi);
            lo = __uint_as_float(__float_as_uint(lo) & 0xFFFFE000u);  // tf32-exact
            o[c] = make_float2(hi, lo);
        }
        g_enorm[code] = acc;
    }
}

// ---------------------------------------------------------------------------
// Kernel 1: tf32x3 mma.sync score GEMM + fused argmin with top-2 tracking
// and exact-fp32 tie repair for rows whose top-2 approx scores are within
// EPS_TIE (covers the <=2-ulp ambiguity of the tf32 approximation).
// ---------------------------------------------------------------------------
__global__ __launch_bounds__(256, 1)
void argmin_kernel(const float* __restrict__ z, const float* __restrict__ emb) {
    extern __shared__ char smem[];
    float2* A2   = (float2*)smem;                    // [128][66]
    float2* B2   = (float2*)(smem + B2_OFF);         // [2][128][66]
    float*  en_s = (float*)(smem + EN_OFF);          // [1024]
    float*  zn_s = (float*)(smem + ZN_OFF);          // [128]
    ULL*    red1 = (ULL*)(smem + RED_OFF);           // [2][128] best
    ULL*    red2 = red1 + 256;                       // [2][128] second best
    const uint32_t sb = smem_u32(smem);

    const int tid  = threadIdx.x;
    const int lane = tid & 31;
    const int wid  = tid >> 5;
    const int wm   = wid & 3;       // row band (32 rows)
    const int wn   = wid >> 2;      // code half (64 codes)
    const int arow = lane >> 2;     // 0..7
    const int acol = lane & 3;      // 0..3

    const int n0  = blockIdx.x * TM;
    const int bB  = n0 >> 12;                     // 128 | 4096: no batch crossing
    const int hw0 = n0 & (HW - 1);
    const float* zb = z + (size_t)bB * CHW + hw0; // zb[k*HW + m]

    // --- A tile: load z, split tf32 hi/lo into A2[m][k] ---
    #pragma unroll
    for (int i = 0; i < 8; i++) {
        int f  = tid + 256 * i;                   // 2048 float4s
        int k  = f >> 5, m4 = f & 31;
        float4 v = *(const float4*)(zb + k * HW + m4 * 4);
        float vv[4] = {v.x, v.y, v.z, v.w};
        #pragma unroll
        for (int j = 0; j < 4; j++) {
            float hi = __uint_as_float(__float_as_uint(vv[j]) & 0xFFFFE000u);
            float lo = __fadd_rn(vv[j], -hi);
            lo = __uint_as_float(__float_as_uint(lo) & 0xFFFFE000u);
            A2[(m4 * 4 + j) * P2 + k] = make_float2(hi, lo);
        }
    }
    // ||z||^2 per row (reference op order); L1-hot from the loads above.
    if (tid < TM) {
        float acc = 0.f;
        const float* p = zb + tid;
        #pragma unroll
        for (int c = 0; c < C; c++) {
            float v = p[c * HW];
            acc = __fadd_rn(acc, __fmul_rn(v, v));
        }
        zn_s[tid] = acc;
    }
    #pragma unroll
    for (int i = 0; i < 4; i++) en_s[tid + 256 * i] = g_enorm[tid + 256 * i];

    // --- cp.async B chunk 0 (pre-split, contiguous per chunk) ---
    {
        const char* src = (const char*)(g_emb2);
        #pragma unroll
        for (int i = 0; i < 16; i++) {
            int q = tid + 256 * i;                // 4096 x 16B
            int code = q >> 5, seg = q & 31;
            uint32_t dst = sb + (uint32_t)(B2_OFF + code * (P2 * 8) + seg * 16);
            cp_async16(dst, src + q * 16);
        }
        asm volatile("cp.async.commit_group;\n");
    }

    // per-thread top-2 packed keys (valbits<<32 | code), d >= 0 so order-safe
    ULL k1[2][2], k2[2][2];
    #pragma unroll
    for (int a = 0; a < 2; a++)
        #pragma unroll
        for (int b = 0; b < 2; b++) { k1[a][b] = ~0ULL; k2[a][b] = ~0ULL; }

    for (int c = 0; c < NCH; c++) {
        // prefetch next chunk into other buffer
        if (c + 1 < NCH) {
            const char* src = (const char*)(g_emb2 + (c + 1) * CH * C);
            const int boff = B2_OFF + ((c + 1) & 1) * B2_BYTES;
            #pragma unroll
            for (int i = 0; i < 16; i++) {
                int q = tid + 256 * i;
                int code = q >> 5, seg = q & 31;
                uint32_t dst = sb + (uint32_t)(boff + code * (P2 * 8) + seg * 16);
                cp_async16(dst, src + q * 16);
            }
            asm volatile("cp.async.commit_group;\n");
            asm volatile("cp.async.wait_group 1;\n");
        } else {
            asm volatile("cp.async.wait_group 0;\n");
        }
        __syncthreads();   // chunk c data + (c==0) prologue stores visible

        const float2* Aw = A2 + (32 * wm) * P2;
        const float2* Bw = B2 + (c & 1) * (CH * P2) + (64 * wn) * P2;

        float acc[2][8][4];
        #pragma unroll
        for (int mi = 0; mi < 2; mi++)
            #pragma unroll
            for (int ni = 0; ni < 8; ni++)
                #pragma unroll
                for (int r = 0; r < 4; r++) acc[mi][ni][r] = 0.f;

        #pragma unroll
        for (int ks = 0; ks < 8; ks++) {
            float2 af[2][4];
            #pragma unroll
            for (int mi = 0; mi < 2; mi++) {
                const float2* Ap = Aw + (16 * mi + arow) * P2 + ks * 8 + acol;
                af[mi][0] = Ap[0];
                af[mi][1] = Ap[8 * P2];
                af[mi][2] = Ap[4];
                af[mi][3] = Ap[8 * P2 + 4];
            }
            float2 bf[8][2];
            #pragma unroll
            for (int ni = 0; ni < 8; ni++) {
                const float2* Bp = Bw + (8 * ni + arow) * P2 + ks * 8 + acol;
                bf[ni][0] = Bp[0];
                bf[ni][1] = Bp[4];
            }
            #pragma unroll
            for (int mi = 0; mi < 2; mi++)
                #pragma unroll
                for (int ni = 0; ni < 8; ni++) {
                    float* d = acc[mi][ni];
                    mma8(d, fu(af[mi][0].x), fu(af[mi][1].x), fu(af[mi][2].x), fu(af[mi][3].x),
                            fu(bf[ni][0].x), fu(bf[ni][1].x));   // hi*hi
                    mma8(d, fu(af[mi][0].x), fu(af[mi][1].x), fu(af[mi][2].x), fu(af[mi][3].x),
                            fu(bf[ni][0].y), fu(bf[ni][1].y));   // hi*lo
                    mma8(d, fu(af[mi][0].y), fu(af[mi][1].y), fu(af[mi][2].y), fu(af[mi][3].y),
                            fu(bf[ni][0].x), fu(bf[ni][1].x));   // lo*hi
                }
        }

        // epilogue: scores -> per-thread top-2
        #pragma unroll
        for (int mi = 0; mi < 2; mi++)
            #pragma unroll
            for (int rh = 0; rh < 2; rh++) {
                int row = 32 * wm + 16 * mi + arow + 8 * rh;
                float zn = zn_s[row];
                #pragma unroll
                for (int ni = 0; ni < 8; ni++)
                    #pragma unroll
                    for (int p = 0; p < 2; p++) {
                        float S = acc[mi][ni][2 * rh + p];
                        int code = c * CH + 64 * wn + 8 * ni + 2 * acol + p;
                        float d = __fadd_rn(__fadd_rn(zn, __fmul_rn(-2.0f, S)), en_s[code]);
                        ULL key = ((ULL)__float_as_uint(d) << 32) | (unsigned)code;
                        if (key < k1[mi][rh]) { k2[mi][rh] = k1[mi][rh]; k1[mi][rh] = key; }
                        else if (key < k2[mi][rh]) { k2[mi][rh] = key; }
                    }
            }
        __syncthreads();   // before next iter's cp.async overwrites buffer
    }

    // reduce top-2 across the 4 acol lanes sharing each row (sorted-pair merge)
    #pragma unroll
    for (int mi = 0; mi < 2; mi++)
        #pragma unroll
        for (int rh = 0; rh < 2; rh++) {
            ULL a1 = k1[mi][rh], a2 = k2[mi][rh];
            #pragma unroll
            for (int m = 1; m <= 2; m <<= 1) {
                ULL o1 = __shfl_xor_sync(0xffffffffu, a1, m);
                ULL o2 = __shfl_xor_sync(0xffffffffu, a2, m);
                ULL n1 = umin(a1, o1);
                ULL n2 = umin(umax(a1, o1), umin(a2, o2));
                a1 = n1; a2 = n2;
            }
            if (acol == 0) {
                int row = 32 * wm + 16 * mi + arow + 8 * rh;
                red1[wn * TM + row] = a1;
                red2[wn * TM + row] = a2;
            }
        }
    __syncthreads();

    // final per-row merge across the two code-halves + tie repair
    if (tid < TM) {
        ULL a1 = red1[tid], a2 = red2[tid];
        ULL b1 = red1[TM + tid], b2 = red2[TM + tid];
        ULL t1 = umin(a1, b1);
        ULL t2 = umin(umax(a1, b1), umin(a2, b2));

        int win = (int)(t1 & 0xffffffffULL);
        float v1 = __uint_as_float((unsigned)(t1 >> 32));
        float v2 = __uint_as_float((unsigned)(t2 >> 32));
        if (v2 - v1 <= EPS_TIE) {
            // exact fp32 re-score of both candidates (exact z/emb from global)
            int c1 = win, c2 = (int)(t2 & 0xffffffffULL);
            const float* zr = zb + tid;
            float zn = zn_s[tid];
            const float* e1 = emb + c1 * C;
            const float* e2 = emb + c2 * C;
            float S1 = 0.f, S2 = 0.f;
            #pragma unroll
            for (int k = 0; k < C; k++) {
                float zv = zr[k * HW];
                S1 = __fmaf_rn(zv, __ldg(e1 + k), S1);
                S2 = __fmaf_rn(zv, __ldg(e2 + k), S2);
            }
            float d1 = __fadd_rn(__fadd_rn(zn, __fmul_rn(-2.0f, S1)), en_s[c1]);
            float d2 = __fadd_rn(__fadd_rn(zn, __fmul_rn(-2.0f, S2)), en_s[c2]);
            if (d2 < d1 || (d2 == d1 && c2 < c1)) win = c2;
        }
        g_idx[n0 + tid] = win;
    }
}

// ---------------------------------------------------------------------------
// Kernel 2: gather codes, straight-through output, partial loss sums.
// ---------------------------------------------------------------------------
__global__ void gather_kernel(const float* __restrict__ z,
                              const float* __restrict__ emb,
                              float* __restrict__ out) {
    int n = blockIdx.x * blockDim.x + threadIdx.x;
    int b = n >> 12, hw = n & (HW - 1);
    const float* zp = z + (size_t)b * CHW + hw;
    float* op = out + (size_t)b * CHW + hw;
    int idx = g_idx[n];
    const float* e = emb + idx * C;

    double s = 0.0;
    #pragma unroll
    for (int c = 0; c < C; c++) {
        float zv   = zp[c * HW];
        float q    = __ldg(e + c);
        float diff = __fadd_rn(q, -zv);
        float qst  = __fadd_rn(zv, diff);
        op[c * HW] = qst;
        s += (double)__fmul_rn(diff, diff);
    }

    __shared__ double sd[256];
    sd[threadIdx.x] = s;
    __syncthreads();
    for (int st = 128; st > 0; st >>= 1) {
        if (threadIdx.x < st) sd[threadIdx.x] += sd[threadIdx.x + st];
        __syncthreads();
    }
    if (threadIdx.x == 0) g_partials[blockIdx.x] = sd[0];
}

// ---------------------------------------------------------------------------
// Kernel 3: parallel deterministic final loss. loss = m + 0.25f*m.
// ---------------------------------------------------------------------------
__global__ void loss_kernel(float* __restrict__ out) {
    __shared__ double sd[256];
    int t = threadIdx.x;
    sd[t] = g_partials[t];
    __syncthreads();
    for (int st = 128; st > 0; st >>= 1) {
        if (t < st) sd[t] += sd[t + st];
        __syncthreads();
    }
    if (t == 0) {
        float m = (float)(sd[0] / (double)((size_t)N * C));
        out[(size_t)N * C] = __fadd_rn(m, 0.25f * m);
    }
}

// ---------------------------------------------------------------------------
extern "C" void kernel_launch(void* const* d_in, const int* in_sizes, int n_in,
                              void* d_out, int out_size) {
    const float* z   = (const float*)d_in[0];   // [16,64,64,64]
    const float* emb = (const float*)d_in[1];   // [1024,64]
    float* out = (float*)d_out;                 // 4194304 q_st + 1 loss

    cudaFuncSetAttribute(argmin_kernel,
                         cudaFuncAttributeMaxDynamicSharedMemorySize, SMEM_BYTES);

    prep_kernel  <<< 4, 256 >>>(emb);
    argmin_kernel<<< N / TM, 256, SMEM_BYTES >>>(z, emb);
    gather_kernel<<< N / 256, 256 >>>(z, emb, out);
    loss_kernel  <<< 1, 256 >>>(out);
}

// round 6
// speedup vs baseline: 1.2930x; 1.2930x over previous
#include <cuda_runtime.h>
#include <cstdint>

typedef unsigned long long ULL;

// Problem constants
constexpr int Bz = 16, C = 64, H = 64, W = 64;
constexpr int N  = Bz * H * W;     // 65536 rows
constexpr int K  = 1024;           // codes
constexpr int HW = H * W;          // 4096
constexpr int CHW = C * HW;        // 262144

// argmin tiling: 128 rows per CTA x 8 chunks of 128 codes
constexpr int TM  = 128;
constexpr int CH  = 128;
constexpr int NCH = K / CH;        // 8

// smem layout (bytes). Scalar tf32 operands, pitch 68 floats
// (bank = 4*arow + acol -> conflict-free fragment LDS.32).
constexpr int PA       = 68;
constexpr int A_BYTES  = TM * PA * 4;            // 34816
constexpr int B_OFF    = A_BYTES;                // 34816
constexpr int B_BYTES  = CH * PA * 4;            // 34816 per buffer (x2)
constexpr int EN_OFF   = B_OFF + 2 * B_BYTES;    // 104448
constexpr int ZN_OFF   = EN_OFF + 4096;          // 108544
constexpr int RED_OFF  = ZN_OFF + 512;           // 109056: ULL red[2][2][128]
constexpr int SMEM_BYTES = RED_OFF + 4096;       // 113152

// Ambiguity window: hard bound on single-pass tf32 |delta d| is ~5e-5;
// EPS = 1.25e-4 covers it with margin. Flagged rows get full exact rescore.
constexpr float EPS_TIE = 1.25e-4f;

// Device scratch (no allocations allowed)
__device__ int    g_idx[N];
__device__ float  g_enorm[K];
__device__ float  g_embt[K * C];     // tf32-truncated emb, [code][k]
__device__ float  g_zn[N];           // exact ||z||^2 per row (reference order)
__device__ int    g_repair_rows[N];
__device__ int    g_repair_count;
__device__ int    g_repair_tick;
__device__ double g_partials[256];

__device__ __forceinline__ uint32_t smem_u32(const void* p) {
    uint32_t a;
    asm("{ .reg .u64 t; cvta.to.shared.u64 t, %1; cvt.u32.u64 %0, t; }" : "=r"(a) : "l"(p));
    return a;
}
__device__ __forceinline__ void cp_async16(uint32_t dst, const void* src) {
    asm volatile("cp.async.cg.shared.global [%0], [%1], 16;\n" :: "r"(dst), "l"(src));
}
__device__ __forceinline__ void mma8(float* d,
                                     uint32_t a0, uint32_t a1, uint32_t a2, uint32_t a3,
                                     uint32_t b0, uint32_t b1) {
    asm volatile("mma.sync.aligned.m16n8k8.row.col.f32.tf32.tf32.f32 "
                 "{%0,%1,%2,%3}, {%4,%5,%6,%7}, {%8,%9}, {%0,%1,%2,%3};"
                 : "+f"(d[0]), "+f"(d[1]), "+f"(d[2]), "+f"(d[3])
                 : "r"(a0), "r"(a1), "r"(a2), "r"(a3), "r"(b0), "r"(b1));
}
__device__ __forceinline__ uint32_t fu(float x) { return __float_as_uint(x); }
__device__ __forceinline__ ULL umin(ULL a, ULL b) { return a < b ? a : b; }
__device__ __forceinline__ ULL umax(ULL a, ULL b) { return a > b ? a : b; }
__device__ __forceinline__ float tf32_trunc(float v) {
    return __uint_as_float(__float_as_uint(v) & 0xFFFFE000u);
}

// ---------------------------------------------------------------------------
// Kernel 0: ||e||^2 (reference rounding), tf32 truncation of emb,
// repair-queue counter reset.
// ---------------------------------------------------------------------------
__global__ void prep_kernel(const float* __restrict__ emb) {
    if (blockIdx.x == 0 && threadIdx.x == 0) { g_repair_count = 0; g_repair_tick = 0; }
    int code = blockIdx.x * blockDim.x + threadIdx.x;   // 0..1023
    if (code < K) {
        const float* e = emb + code * C;
        float* o = g_embt + code * C;
        float acc = 0.f;
        #pragma unroll
        for (int c = 0; c < C; c++) {
            float v = e[c];
            acc = __fadd_rn(acc, __fmul_rn(v, v));
            o[c] = tf32_trunc(v);
        }
        g_enorm[code] = acc;
    }
}

// ---------------------------------------------------------------------------
// Kernel 1: single-pass tf32 mma.sync score GEMM + fused argmin (top-2).
// Rows whose approx top-2 gap <= EPS_TIE are enqueued for exact rescore.
// ---------------------------------------------------------------------------
__global__ __launch_bounds__(256, 1)
void argmin_kernel(const float* __restrict__ z) {
    extern __shared__ char smem[];
    float* A2   = (float*)smem;                      // [128][68]
    float* B2   = (float*)(smem + B_OFF);            // [2][128][68]
    float* en_s = (float*)(smem + EN_OFF);           // [1024]
    float* zn_s = (float*)(smem + ZN_OFF);           // [128]
    ULL*   red1 = (ULL*)(smem + RED_OFF);            // [2][128] best
    ULL*   red2 = red1 + 256;                        // [2][128] second best
    const uint32_t sb = smem_u32(smem);

    const int tid  = threadIdx.x;
    const int lane = tid & 31;
    const int wid  = tid >> 5;
    const int wm   = wid & 3;       // row band (32 rows)
    const int wn   = wid >> 2;      // code half (64 codes)
    const int arow = lane >> 2;     // 0..7
    const int acol = lane & 3;      // 0..3

    const int n0  = blockIdx.x * TM;
    const int bB  = n0 >> 12;                     // 128 | 4096: no batch crossing
    const int hw0 = n0 & (HW - 1);
    const float* zb = z + (size_t)bB * CHW + hw0; // zb[k*HW + m]

    // --- A tile: load z, tf32-truncate into A2[m][k] ---
    #pragma unroll
    for (int i = 0; i < 8; i++) {
        int f  = tid + 256 * i;                   // 2048 float4s
        int k  = f >> 5, m4 = f & 31;
        float4 v = *(const float4*)(zb + k * HW + m4 * 4);
        float vv[4] = {v.x, v.y, v.z, v.w};
        #pragma unroll
        for (int j = 0; j < 4; j++)
            A2[(m4 * 4 + j) * PA + k] = tf32_trunc(vv[j]);
    }
    // ||z||^2 per row (reference op order); L1-hot from the loads above.
    if (tid < TM) {
        float acc = 0.f;
        const float* p = zb + tid;
        #pragma unroll
        for (int c = 0; c < C; c++) {
            float v = p[c * HW];
            acc = __fadd_rn(acc, __fmul_rn(v, v));
        }
        zn_s[tid] = acc;
        g_zn[n0 + tid] = acc;                     // exact zn for repair kernel
    }
    #pragma unroll
    for (int i = 0; i < 4; i++) en_s[tid + 256 * i] = g_enorm[tid + 256 * i];

    // --- cp.async B chunk 0 (pre-truncated, contiguous 32KB per chunk) ---
    {
        const char* src = (const char*)g_embt;
        #pragma unroll
        for (int i = 0; i < 8; i++) {
            int q = tid + 256 * i;                // 2048 x 16B
            int code = q >> 4, seg = q & 15;
            uint32_t dst = sb + (uint32_t)(B_OFF + code * (PA * 4) + seg * 16);
            cp_async16(dst, src + q * 16);
        }
        asm volatile("cp.async.commit_group;\n");
    }

    // per-thread top-2 packed keys (valbits<<32 | code); d >= 0 so order-safe
    ULL k1[2][2], k2[2][2];
    #pragma unroll
    for (int a = 0; a < 2; a++)
        #pragma unroll
        for (int b = 0; b < 2; b++) { k1[a][b] = ~0ULL; k2[a][b] = ~0ULL; }

    for (int c = 0; c < NCH; c++) {
        // prefetch next chunk into other buffer
        if (c + 1 < NCH) {
            const char* src = (const char*)(g_embt + (c + 1) * CH * C);
            const int boff = B_OFF + ((c + 1) & 1) * B_BYTES;
            #pragma unroll
            for (int i = 0; i < 8; i++) {
                int q = tid + 256 * i;
                int code = q >> 4, seg = q & 15;
                uint32_t dst = sb + (uint32_t)(boff + code * (PA * 4) + seg * 16);
                cp_async16(dst, src + q * 16);
            }
            asm volatile("cp.async.commit_group;\n");
            asm volatile("cp.async.wait_group 1;\n");
        } else {
            asm volatile("cp.async.wait_group 0;\n");
        }
        __syncthreads();   // chunk c data + (c==0) prologue stores visible

        const float* Aw = A2 + (32 * wm) * PA;
        const float* Bw = B2 + (c & 1) * (CH * PA) + (64 * wn) * PA;

        float acc[2][8][4];
        #pragma unroll
        for (int mi = 0; mi < 2; mi++)
            #pragma unroll
            for (int ni = 0; ni < 8; ni++)
                #pragma unroll
                for (int r = 0; r < 4; r++) acc[mi][ni][r] = 0.f;

        #pragma unroll
        for (int ks = 0; ks < 8; ks++) {
            float af[2][4];
            #pragma unroll
            for (int mi = 0; mi < 2; mi++) {
                const float* Ap = Aw + (16 * mi + arow) * PA + ks * 8 + acol;
                af[mi][0] = Ap[0];
                af[mi][1] = Ap[8 * PA];
                af[mi][2] = Ap[4];
                af[mi][3] = Ap[8 * PA + 4];
            }
            float bf[8][2];
            #pragma unroll
            for (int ni = 0; ni < 8; ni++) {
                const float* Bp = Bw + (8 * ni + arow) * PA + ks * 8 + acol;
                bf[ni][0] = Bp[0];
                bf[ni][1] = Bp[4];
            }
            #pragma unroll
            for (int mi = 0; mi < 2; mi++)
                #pragma unroll
                for (int ni = 0; ni < 8; ni++)
                    mma8(acc[mi][ni],
                         fu(af[mi][0]), fu(af[mi][1]), fu(af[mi][2]), fu(af[mi][3]),
                         fu(bf[ni][0]), fu(bf[ni][1]));
        }

        // epilogue: scores -> per-thread top-2
        #pragma unroll
        for (int mi = 0; mi < 2; mi++)
            #pragma unroll
            for (int rh = 0; rh < 2; rh++) {
                int row = 32 * wm + 16 * mi + arow + 8 * rh;
                float zn = zn_s[row];
                #pragma unroll
                for (int ni = 0; ni < 8; ni++)
                    #pragma unroll
                    for (int p = 0; p < 2; p++) {
                        float S = acc[mi][ni][2 * rh + p];
                        int code = c * CH + 64 * wn + 8 * ni + 2 * acol + p;
                        float d = __fadd_rn(__fadd_rn(zn, __fmul_rn(-2.0f, S)), en_s[code]);
                        ULL key = ((ULL)__float_as_uint(d) << 32) | (unsigned)code;
                        if (key < k1[mi][rh]) { k2[mi][rh] = k1[mi][rh]; k1[mi][rh] = key; }
                        else if (key < k2[mi][rh]) { k2[mi][rh] = key; }
                    }
            }
        __syncthreads();   // before next iter's cp.async overwrites buffer
    }

    // reduce top-2 across the 4 acol lanes sharing each row
    #pragma unroll
    for (int mi = 0; mi < 2; mi++)
        #pragma unroll
        for (int rh = 0; rh < 2; rh++) {
            ULL a1 = k1[mi][rh], a2 = k2[mi][rh];
            #pragma unroll
            for (int m = 1; m <= 2; m <<= 1) {
                ULL o1 = __shfl_xor_sync(0xffffffffu, a1, m);
                ULL o2 = __shfl_xor_sync(0xffffffffu, a2, m);
                ULL n1 = umin(a1, o1);
                ULL n2 = umin(umax(a1, o1), umin(a2, o2));
                a1 = n1; a2 = n2;
            }
            if (acol == 0) {
                int row = 32 * wm + 16 * mi + arow + 8 * rh;
                red1[wn * TM + row] = a1;
                red2[wn * TM + row] = a2;
            }
        }
    __syncthreads();

    // final per-row merge across the two code-halves + ambiguity flagging
    if (tid < TM) {
        ULL a1 = red1[tid], a2 = red2[tid];
        ULL b1 = red1[TM + tid], b2 = red2[TM + tid];
        ULL t1 = umin(a1, b1);
        ULL t2 = umin(umax(a1, b1), umin(a2, b2));

        g_idx[n0 + tid] = (int)(t1 & 0xffffffffULL);   // provisional winner
        float v1 = __uint_as_float((unsigned)(t1 >> 32));
        float v2 = __uint_as_float((unsigned)(t2 >> 32));
        if (v2 - v1 <= EPS_TIE) {
            int pos = atomicAdd(&g_repair_count, 1);
            g_repair_rows[pos] = n0 + tid;
        }
    }
}

// ---------------------------------------------------------------------------
// Kernel 1b: exact full rescore of flagged rows (all 1024 codes).
// S via sequential fp32 fmaf over k (the formula that matched the reference
// bit-for-bit in earlier rounds); min by lexicographic (d, code).
// Blocks batch 16 rows and share the emb scan through smem.
// ---------------------------------------------------------------------------
__global__ __launch_bounds__(256) void repair_kernel(const float* __restrict__ z,
                                                     const float* __restrict__ emb) {
    __shared__ float es[128 * 65];    // emb chunk, pitch 65 (conflict-free)
    __shared__ float ze[16 * 66];     // z rows, pitch 66
    __shared__ float zn_sh[16];
    __shared__ int   rows_sh[16];
    __shared__ int   s_base;

    const int tid = threadIdx.x;
    const int r   = tid >> 4;         // row slot 0..15
    const int cc  = tid & 15;         // code lane 0..15

    for (;;) {
        if (tid == 0) s_base = atomicAdd(&g_repair_tick, 16);
        __syncthreads();
        const int base = s_base;
        const int cnt  = g_repair_count;
        if (base >= cnt) break;
        const int nrows = min(16, cnt - base);

        if (tid < nrows) {
            int n = g_repair_rows[base + tid];
            rows_sh[tid] = n;
            zn_sh[tid]   = g_zn[n];
        }
        __syncthreads();
        #pragma unroll
        for (int i = 0; i < 4; i++) {
            int e2 = tid + 256 * i;               // 1024 elems
            int rr = e2 >> 6, k = e2 & 63;
            if (rr < nrows) {
                int n = rows_sh[rr], b = n >> 12, hw = n & (HW - 1);
                ze[rr * 66 + k] = z[(size_t)b * CHW + k * HW + hw];
            }
        }
        __syncthreads();

        ULL best = ~0ULL;
        for (int ch = 0; ch < 8; ch++) {
            #pragma unroll
            for (int i = 0; i < 32; i++) {        // 8192 floats
                int f = tid + 256 * i;
                int code = f >> 6, k = f & 63;
                es[code * 65 + k] = emb[ch * 8192 + f];
            }
            __syncthreads();
            if (r < nrows) {
                float S[8];
                #pragma unroll
                for (int j = 0; j < 8; j++) S[j] = 0.f;
                #pragma unroll 8
                for (int k = 0; k < 64; k++) {
                    float zk = ze[r * 66 + k];
                    #pragma unroll
                    for (int j = 0; j < 8; j++)
                        S[j] = __fmaf_rn(zk, es[(cc + 16 * j) * 65 + k], S[j]);
                }
                float zn = zn_sh[r];
                #pragma unroll
                for (int j = 0; j < 8; j++) {
                    int code = ch * 128 + cc + 16 * j;
                    float d = __fadd_rn(__fadd_rn(zn, __fmul_rn(-2.0f, S[j])), g_enorm[code]);
                    ULL key = ((ULL)__float_as_uint(d) << 32) | (unsigned)code;
                    if (key < best) best = key;
                }
            }
            __syncthreads();
        }
        // reduce across the 16 lanes sharing a row (xor masks stay in-group)
        #pragma unroll
        for (int m = 1; m < 16; m <<= 1) {
            ULL o = __shfl_xor_sync(0xffffffffu, best, m);
            if (o < best) best = o;
        }
        if (cc == 0 && r < nrows) g_idx[rows_sh[r]] = (int)(best & 0xffffffffULL);
        __syncthreads();
    }
}

// ---------------------------------------------------------------------------
// Kernel 2: gather codes, straight-through output, partial loss sums.
// ---------------------------------------------------------------------------
__global__ void gather_kernel(const float* __restrict__ z,
                              const float* __restrict__ emb,
                              float* __restrict__ out) {
    int n = blockIdx.x * blockDim.x + threadIdx.x;
    int b = n >> 12, hw = n & (HW - 1);
    const float* zp = z + (size_t)b * CHW + hw;
    float* op = out + (size_t)b * CHW + hw;
    int idx = g_idx[n];
    const float* e = emb + idx * C;

    double s = 0.0;
    #pragma unroll
    for (int c = 0; c < C; c++) {
        float zv   = zp[c * HW];
        float q    = __ldg(e + c);
        float diff = __fadd_rn(q, -zv);
        float qst  = __fadd_rn(zv, diff);
        op[c * HW] = qst;
        s += (double)__fmul_rn(diff, diff);
    }

    __shared__ double sd[256];
    sd[threadIdx.x] = s;
    __syncthreads();
    for (int st = 128; st > 0; st >>= 1) {
        if (threadIdx.x < st) sd[threadIdx.x] += sd[threadIdx.x + st];
        __syncthreads();
    }
    if (threadIdx.x == 0) g_partials[blockIdx.x] = sd[0];
}

// ---------------------------------------------------------------------------
// Kernel 3: parallel deterministic final loss. loss = m + 0.25f*m.
// ---------------------------------------------------------------------------
__global__ void loss_kernel(float* __restrict__ out) {
    __shared__ double sd[256];
    int t = threadIdx.x;
    sd[t] = g_partials[t];
    __syncthreads();
    for (int st = 128; st > 0; st >>= 1) {
        if (t < st) sd[t] += sd[t + st];
        __syncthreads();
    }
    if (t == 0) {
        float m = (float)(sd[0] / (double)((size_t)N * C));
        out[(size_t)N * C] = __fadd_rn(m, 0.25f * m);
    }
}

// ---------------------------------------------------------------------------
extern "C" void kernel_launch(void* const* d_in, const int* in_sizes, int n_in,
                              void* d_out, int out_size) {
    const float* z   = (const float*)d_in[0];   // [16,64,64,64]
    const float* emb = (const float*)d_in[1];   // [1024,64]
    float* out = (float*)d_out;                 // 4194304 q_st + 1 loss

    cudaFuncSetAttribute(argmin_kernel,
                         cudaFuncAttributeMaxDynamicSharedMemorySize, SMEM_BYTES);

    prep_kernel  <<< 4, 256 >>>(emb);
    argmin_kernel<<< N / TM, 256, SMEM_BYTES >>>(z);
    repair_kernel<<< 128, 256 >>>(z, emb);
    gather_kernel<<< N / 256, 256 >>>(z, emb, out);
    loss_kernel  <<< 1, 256 >>>(out);
}

// round 9
// speedup vs baseline: 1.5379x; 1.1894x over previous
#include <cuda_runtime.h>
#include <cuda_fp16.h>
#include <cstdint>

typedef unsigned long long ULL;

// Problem constants
constexpr int Bz = 16, C = 64, H = 64, W = 64;
constexpr int N  = Bz * H * W;     // 65536 rows
constexpr int K  = 1024;           // codes
constexpr int HW = H * W;          // 4096
constexpr int CHW = C * HW;        // 262144

// argmin tiling: 128 rows per CTA x 8 chunks of 128 codes
constexpr int TM  = 128;
constexpr int CH  = 128;
constexpr int NCH = K / CH;        // 8

// smem layout (bytes). Operands are half2 (uint32) with pitch 36 u32:
// fragment bank = (row*36 + kp) mod 32 = 4*arow + acol -> conflict-free.
constexpr int PW       = 36;                     // pitch in u32
constexpr int A_BYTES  = TM * PW * 4;            // 18432
constexpr int B_OFF    = A_BYTES;                // 18432
constexpr int B_BYTES  = CH * PW * 4;            // 18432 per buffer (x2)
constexpr int EN_OFF   = B_OFF + 2 * B_BYTES;    // 55296
constexpr int ZN_OFF   = EN_OFF + 4096;          // 59392
constexpr int RED_OFF  = ZN_OFF + 512;           // 59904: ULL red1[2][128]
constexpr int RED2_OFF = RED_OFF + 2048;         // 61952: float red2[2][128]
constexpr int SMEM_BYTES = RED2_OFF + 1024;      // 62976

// Ambiguity window: fp16-rn single-pass |delta d| is ~1e-5 rms, <=~5e-5 in
// pathological alignment. Flagged rows get a full exact-fp32 rescore.
constexpr float EPS_TIE = 1.5e-4f;

// Device scratch (no allocations allowed)
__device__ int      g_idx[N];
__device__ float    g_enorm[K];
__device__ uint32_t g_embh[K * (C / 2)];   // half2-packed emb, [code][kpair]
__device__ float    g_zn[N];               // exact ||z||^2 (reference order)
__device__ int      g_repair_rows[N];
__device__ int      g_repair_count;
__device__ int      g_repair_tick;
__device__ double   g_partials[1024];

__device__ __forceinline__ uint32_t smem_u32(const void* p) {
    uint32_t a;
    asm("{ .reg .u64 t; cvta.to.shared.u64 t, %1; cvt.u32.u64 %0, t; }" : "=r"(a) : "l"(p));
    return a;
}
__device__ __forceinline__ void cp_async16(uint32_t dst, const void* src) {
    asm volatile("cp.async.cg.shared.global [%0], [%1], 16;\n" :: "r"(dst), "l"(src));
}
// m16n8k16 f16 mma, f32 accumulate
__device__ __forceinline__ void mma16(float* d,
                                      uint32_t a0, uint32_t a1, uint32_t a2, uint32_t a3,
                                      uint32_t b0, uint32_t b1) {
    asm volatile("mma.sync.aligned.m16n8k16.row.col.f32.f16.f16.f32 "
                 "{%0,%1,%2,%3}, {%4,%5,%6,%7}, {%8,%9}, {%0,%1,%2,%3};"
                 : "+f"(d[0]), "+f"(d[1]), "+f"(d[2]), "+f"(d[3])
                 : "r"(a0), "r"(a1), "r"(a2), "r"(a3), "r"(b0), "r"(b1));
}
__device__ __forceinline__ ULL umin(ULL a, ULL b) { return a < b ? a : b; }
__device__ __forceinline__ uint32_t pack_h2(float x, float y) {
    __half2 h = __floats2half2_rn(x, y);
    return *(uint32_t*)&h;
}

// ---------------------------------------------------------------------------
// Kernel 0: ||e||^2 (reference rounding), half2 packing of emb, counters.
// ---------------------------------------------------------------------------
__global__ void prep_kernel(const float* __restrict__ emb) {
    if (blockIdx.x == 0 && threadIdx.x == 0) { g_repair_count = 0; g_repair_tick = 0; }
    int code = blockIdx.x * blockDim.x + threadIdx.x;   // 0..1023
    if (code < K) {
        const float* e = emb + code * C;
        uint32_t* o = g_embh + code * (C / 2);
        float acc = 0.f;
        #pragma unroll
        for (int c = 0; c < C; c++) {
            float v = e[c];
            acc = __fadd_rn(acc, __fmul_rn(v, v));
        }
        #pragma unroll
        for (int kp = 0; kp < C / 2; kp++)
            o[kp] = pack_h2(e[2 * kp], e[2 * kp + 1]);
        g_enorm[code] = acc;
    }
}

// ---------------------------------------------------------------------------
// Kernel 1: single-pass fp16 mma score GEMM + fused argmin.
// Tracks (best packed key, second-best value); rows with approx gap <=
// EPS_TIE are enqueued for exact rescore. Occupancy 2.
// ---------------------------------------------------------------------------
__global__ __launch_bounds__(256, 2)
void argmin_kernel(const float* __restrict__ z) {
    extern __shared__ char smem[];
    uint32_t* A2   = (uint32_t*)smem;                 // [128][36] half2
    uint32_t* B2   = (uint32_t*)(smem + B_OFF);       // [2][128][36]
    float*    en_s = (float*)(smem + EN_OFF);         // [1024]
    float*    zn_s = (float*)(smem + ZN_OFF);         // [128]
    ULL*      red1 = (ULL*)(smem + RED_OFF);          // [2][128] best key
    float*    red2 = (float*)(smem + RED2_OFF);       // [2][128] 2nd value
    const uint32_t sb = smem_u32(smem);

    const int tid  = threadIdx.x;
    const int lane = tid & 31;
    const int wid  = tid >> 5;
    const int wm   = wid & 3;       // row band (32 rows)
    const int wn   = wid >> 2;      // code half (64 codes)
    const int arow = lane >> 2;     // 0..7
    const int acol = lane & 3;      // 0..3

    const int n0  = blockIdx.x * TM;
    const int bB  = n0 >> 12;                     // 128 | 4096: no batch crossing
    const int hw0 = n0 & (HW - 1);
    const float* zb = z + (size_t)bB * CHW + hw0; // zb[k*HW + m]

    // --- A tile: z -> half2 pairs A2[m][kp]; FULL 128 rows x 32 kp ---
    #pragma unroll
    for (int i = 0; i < 16; i++) {
        int f  = tid + 256 * i;                   // 4096 (kp, m) pairs
        int m  = f & 127, kp = f >> 7;            // m 0..127, kp 0..31
        float v0 = zb[(2 * kp) * HW + m];
        float v1 = zb[(2 * kp + 1) * HW + m];
        A2[m * PW + kp] = pack_h2(v0, v1);
    }
    // ||z||^2 per row (reference op order); L1-hot from the loads above.
    if (tid < TM) {
        float acc = 0.f;
        const float* p = zb + tid;
        #pragma unroll
        for (int c = 0; c < C; c++) {
            float v = p[c * HW];
            acc = __fadd_rn(acc, __fmul_rn(v, v));
        }
        zn_s[tid] = acc;
        g_zn[n0 + tid] = acc;
    }
    #pragma unroll
    for (int i = 0; i < 4; i++) en_s[tid + 256 * i] = g_enorm[tid + 256 * i];

    // --- cp.async B chunk 0 (pre-packed half2, 128B per code row) ---
    {
        const char* src = (const char*)g_embh;
        #pragma unroll
        for (int i = 0; i < 4; i++) {
            int q = tid + 256 * i;                // 1024 x 16B
            int code = q >> 3, seg = q & 7;
            uint32_t dst = sb + (uint32_t)(B_OFF + code * (PW * 4) + seg * 16);
            cp_async16(dst, src + q * 16);
        }
        asm volatile("cp.async.commit_group;\n");
    }

    // per-thread: best packed key (valbits<<32|code) + second-best value
    ULL   k1[2][2];
    float v2[2][2];
    #pragma unroll
    for (int a = 0; a < 2; a++)
        #pragma unroll
        for (int b = 0; b < 2; b++) { k1[a][b] = ~0ULL; v2[a][b] = 3.4e38f; }

    for (int c = 0; c < NCH; c++) {
        if (c + 1 < NCH) {
            const char* src = (const char*)(g_embh + (c + 1) * CH * (C / 2));
            const int boff = B_OFF + ((c + 1) & 1) * B_BYTES;
            #pragma unroll
            for (int i = 0; i < 4; i++) {
                int q = tid + 256 * i;
                int code = q >> 3, seg = q & 7;
                uint32_t dst = sb + (uint32_t)(boff + code * (PW * 4) + seg * 16);
                cp_async16(dst, src + q * 16);
            }
            asm volatile("cp.async.commit_group;\n");
            asm volatile("cp.async.wait_group 1;\n");
        } else {
            asm volatile("cp.async.wait_group 0;\n");
        }
        __syncthreads();   // chunk c data + (c==0) prologue stores visible

        const uint32_t* Aw = A2 + (32 * wm) * PW;
        const uint32_t* Bw = B2 + (c & 1) * (CH * PW) + (64 * wn) * PW;

        float acc[2][8][4];
        #pragma unroll
        for (int mi = 0; mi < 2; mi++)
            #pragma unroll
            for (int ni = 0; ni < 8; ni++)
                #pragma unroll
                for (int r = 0; r < 4; r++) acc[mi][ni][r] = 0.f;

        #pragma unroll
        for (int ks = 0; ks < 4; ks++) {          // 4 k-steps of 16
            uint32_t af[2][4];
            #pragma unroll
            for (int mi = 0; mi < 2; mi++) {
                const uint32_t* Ap = Aw + (16 * mi + arow) * PW + ks * 8 + acol;
                af[mi][0] = Ap[0];
                af[mi][1] = Ap[8 * PW];
                af[mi][2] = Ap[4];
                af[mi][3] = Ap[8 * PW + 4];
            }
            uint32_t bf[8][2];
            #pragma unroll
            for (int ni = 0; ni < 8; ni++) {
                const uint32_t* Bp = Bw + (8 * ni + arow) * PW + ks * 8 + acol;
                bf[ni][0] = Bp[0];
                bf[ni][1] = Bp[4];
            }
            #pragma unroll
            for (int mi = 0; mi < 2; mi++)
                #pragma unroll
                for (int ni = 0; ni < 8; ni++)
                    mma16(acc[mi][ni],
                          af[mi][0], af[mi][1], af[mi][2], af[mi][3],
                          bf[ni][0], bf[ni][1]);
        }

        // epilogue: scores -> per-thread (best, second-value)
        #pragma unroll
        for (int mi = 0; mi < 2; mi++)
            #pragma unroll
            for (int rh = 0; rh < 2; rh++) {
                int row = 32 * wm + 16 * mi + arow + 8 * rh;
                float zn = zn_s[row];
                #pragma unroll
                for (int ni = 0; ni < 8; ni++)
                    #pragma unroll
                    for (int p = 0; p < 2; p++) {
                        float S = acc[mi][ni][2 * rh + p];
                        int code = c * CH + 64 * wn + 8 * ni + 2 * acol + p;
                        float d = __fadd_rn(__fadd_rn(zn, __fmul_rn(-2.0f, S)), en_s[code]);
                        ULL key = ((ULL)__float_as_uint(d) << 32) | (unsigned)code;
                        if (key < k1[mi][rh]) {
                            v2[mi][rh] = __uint_as_float((unsigned)(k1[mi][rh] >> 32));
                            k1[mi][rh] = key;
                        } else if (d < v2[mi][rh]) {
                            v2[mi][rh] = d;
                        }
                    }
            }
        __syncthreads();   // before next iter's cp.async overwrites buffer
    }

    // reduce (best, second-value) across the 4 acol lanes sharing each row
    #pragma unroll
    for (int mi = 0; mi < 2; mi++)
        #pragma unroll
        for (int rh = 0; rh < 2; rh++) {
            ULL   a1 = k1[mi][rh];
            float a2 = v2[mi][rh];
            #pragma unroll
            for (int m = 1; m <= 2; m <<= 1) {
                ULL   o1 = __shfl_xor_sync(0xffffffffu, a1, m);
                float o2 = __shfl_xor_sync(0xffffffffu, a2, m);
                // loser-best's value competes for second place
                float lv = __uint_as_float((unsigned)((a1 > o1 ? a1 : o1) >> 32));
                a2 = fminf(fminf(a2, o2), lv);
                a1 = umin(a1, o1);
            }
            if (acol == 0) {
                int row = 32 * wm + 16 * mi + arow + 8 * rh;
                red1[wn * TM + row] = a1;
                red2[wn * TM + row] = a2;
            }
        }
    __syncthreads();

    // final per-row merge across the two code-halves + ambiguity flagging
    if (tid < TM) {
        ULL   a1 = red1[tid],      b1 = red1[TM + tid];
        float a2 = red2[tid],      b2 = red2[TM + tid];
        ULL t1 = umin(a1, b1);
        float lv = __uint_as_float((unsigned)((a1 > b1 ? a1 : b1) >> 32));
        float sv = fminf(fminf(a2, b2), lv);

        g_idx[n0 + tid] = (int)(t1 & 0xffffffffULL);   // provisional winner
        float v1 = __uint_as_float((unsigned)(t1 >> 32));
        if (sv - v1 <= EPS_TIE) {
            int pos = atomicAdd(&g_repair_count, 1);
            g_repair_rows[pos] = n0 + tid;
        }
    }
}

// ---------------------------------------------------------------------------
// Kernel 1b: exact full rescore of flagged rows (all 1024 codes), exact
// fp32 fmaf dot (formula validated earlier); min by lexicographic (d, code).
// ---------------------------------------------------------------------------
__global__ __launch_bounds__(256) void repair_kernel(const float* __restrict__ z,
                                                     const float* __restrict__ emb) {
    __shared__ float es[128 * 65];    // emb chunk, pitch 65 (conflict-free)
    __shared__ float ze[16 * 66];     // z rows, pitch 66
    __shared__ float zn_sh[16];
    __shared__ int   rows_sh[16];
    __shared__ int   s_base;

    const int tid = threadIdx.x;
    const int r   = tid >> 4;         // row slot 0..15
    const int cc  = tid & 15;         // code lane 0..15

    for (;;) {
        if (tid == 0) s_base = atomicAdd(&g_repair_tick, 16);
        __syncthreads();
        const int base = s_base;
        const int cnt  = g_repair_count;
        if (base >= cnt) break;
        const int nrows = min(16, cnt - base);

        if (tid < nrows) {
            int n = g_repair_rows[base + tid];
            rows_sh[tid] = n;
            zn_sh[tid]   = g_zn[n];
        }
        __syncthreads();
        #pragma unroll
        for (int i = 0; i < 4; i++) {
            int e2 = tid + 256 * i;               // 1024 elems
            int rr = e2 >> 6, k = e2 & 63;
            if (rr < nrows) {
                int n = rows_sh[rr], b = n >> 12, hw = n & (HW - 1);
                ze[rr * 66 + k] = z[(size_t)b * CHW + k * HW + hw];
            }
        }
        __syncthreads();

        ULL best = ~0ULL;
        for (int ch = 0; ch < 8; ch++) {
            #pragma unroll
            for (int i = 0; i < 32; i++) {        // 8192 floats
                int f = tid + 256 * i;
                int code = f >> 6, k = f & 63;
                es[code * 65 + k] = emb[ch * 8192 + f];
            }
            __syncthreads();
            if (r < nrows) {
                float S[8];
                #pragma unroll
                for (int j = 0; j < 8; j++) S[j] = 0.f;
                #pragma unroll 8
                for (int k = 0; k < 64; k++) {
                    float zk = ze[r * 66 + k];
                    #pragma unroll
                    for (int j = 0; j < 8; j++)
                        S[j] = __fmaf_rn(zk, es[(cc + 16 * j) * 65 + k], S[j]);
                }
                float zn = zn_sh[r];
                #pragma unroll
                for (int j = 0; j < 8; j++) {
                    int code = ch * 128 + cc + 16 * j;
                    float d = __fadd_rn(__fadd_rn(zn, __fmul_rn(-2.0f, S[j])), g_enorm[code]);
                    ULL key = ((ULL)__float_as_uint(d) << 32) | (unsigned)code;
                    if (key < best) best = key;
                }
            }
            __syncthreads();
        }
        #pragma unroll
        for (int m = 1; m < 16; m <<= 1) {
            ULL o = __shfl_xor_sync(0xffffffffu, best, m);
            if (o < best) best = o;
        }
        if (cc == 0 && r < nrows) g_idx[rows_sh[r]] = (int)(best & 0xffffffffULL);
        __syncthreads();
    }
}

// ---------------------------------------------------------------------------
// Kernel 2: gather codes, straight-through output, partial loss sums.
// 4 threads per row (16 channels each) for latency hiding; 1024 blocks.
// ---------------------------------------------------------------------------
__global__ __launch_bounds__(256) void gather_kernel(const float* __restrict__ z,
                                                     const float* __restrict__ emb,
                                                     float* __restrict__ out) {
    const int tid = threadIdx.x;
    const int m   = tid & 63;          // row within block band
    const int cg  = tid >> 6;          // channel group 0..3
    const int n   = blockIdx.x * 64 + m;
    const int b   = n >> 12, hw = n & (HW - 1);
    const float* zp = z + (size_t)b * CHW + hw;
    float* op = out + (size_t)b * CHW + hw;
    const int idx = g_idx[n];
    const float* e = emb + idx * C + cg * 16;

    double s = 0.0;
    #pragma unroll
    for (int i = 0; i < 16; i++) {
        int c = cg * 16 + i;
        float zv   = zp[c * HW];
        float q    = __ldg(e + i);
        float diff = __fadd_rn(q, -zv);
        float qst  = __fadd_rn(zv, diff);
        op[c * HW] = qst;
        s += (double)__fmul_rn(diff, diff);
    }

    __shared__ double sd[256];
    sd[tid] = s;
    __syncthreads();
    for (int st = 128; st > 0; st >>= 1) {
        if (tid < st) sd[tid] += sd[tid + st];
        __syncthreads();
    }
    if (tid == 0) g_partials[blockIdx.x] = sd[0];
}

// ---------------------------------------------------------------------------
// Kernel 3: parallel deterministic final loss. loss = m + 0.25f*m.
// ---------------------------------------------------------------------------
__global__ void loss_kernel(float* __restrict__ out) {
    __shared__ double sd[256];
    int t = threadIdx.x;
    double s = 0.0;
    #pragma unroll
    for (int i = 0; i < 4; i++) s += g_partials[t + 256 * i];
    sd[t] = s;
    __syncthreads();
    for (int st = 128; st > 0; st >>= 1) {
        if (t < st) sd[t] += sd[t + st];
        __syncthreads();
    }
    if (t == 0) {
        float m = (float)(sd[0] / (double)((size_t)N * C));
        out[(size_t)N * C] = __fadd_rn(m, 0.25f * m);
    }
}

// ---------------------------------------------------------------------------
extern "C" void kernel_launch(void* const* d_in, const int* in_sizes, int n_in,
                              void* d_out, int out_size) {
    const float* z   = (const float*)d_in[0];   // [16,64,64,64]
    const float* emb = (const float*)d_in[1];   // [1024,64]
    float* out = (float*)d_out;                 // 4194304 q_st + 1 loss

    cudaFuncSetAttribute(argmin_kernel,
                         cudaFuncAttributeMaxDynamicSharedMemorySize, SMEM_BYTES);

    prep_kernel  <<< 4, 256 >>>(emb);
    argmin_kernel<<< N / TM, 256, SMEM_BYTES >>>(z);
    repair_kernel<<< 128, 256 >>>(z, emb);
    gather_kernel<<< N / 64, 256 >>>(z, emb, out);
    loss_kernel  <<< 1, 256 >>>(out);
}

// round 11
// speedup vs baseline: 1.8893x; 1.2285x over previous
#include <cuda_runtime.h>
#include <cuda_fp16.h>
#include <cstdint>

typedef unsigned long long ULL;

// Problem constants
constexpr int Bz = 16, C = 64, H = 64, W = 64;
constexpr int N  = Bz * H * W;     // 65536 rows
constexpr int K  = 1024;           // codes
constexpr int HW = H * W;          // 4096
constexpr int CHW = C * HW;        // 262144

// argmin tiling: 128 rows per CTA x 8 chunks of 128 codes
constexpr int TM  = 128;
constexpr int CH  = 128;
constexpr int NCH = K / CH;        // 8

// smem layout (bytes). Operands half2 (u32), pitch 36 u32 (conflict-free frags).
constexpr int PW       = 36;
constexpr int A_BYTES  = TM * PW * 4;            // 18432
constexpr int B_OFF    = A_BYTES;                // 18432
constexpr int B_BYTES  = CH * PW * 4;            // 18432 per buffer (x3)
constexpr int ENS_OFF  = B_OFF + 3 * B_BYTES;    // 73728: biased norms [1024] f32
constexpr int RED_OFF  = ENS_OFF + 4096;         // 77824: u32 red1[256], red2[256]
constexpr int SMEM_BYTES = RED_OFF + 2048;       // 79872

// Flag window: fp16 score noise (<=1.5e-4, 21-sigma proven in R9) + 32-bit
// key quantization (<=3.1e-5). Flagged rows get full exact-fp32 rescore.
constexpr float EPS_TIE = 1.81e-4f;
constexpr float VAL_BIAS = 0.1f;   // keeps val positive -> monotone float bits

// Device scratch (no allocations allowed)
__device__ int      g_idx[N];
__device__ float    g_enorm[K];            // exact ||e||^2 (reference rounding)
__device__ float    g_ens[K];              // VAL_BIAS + ||e||^2
__device__ uint32_t g_embh[K * (C / 2)];   // half2-packed emb, [code][kpair]
__device__ float    g_zn[N];               // exact ||z||^2 (reference order)
__device__ int      g_repair_rows[N];
__device__ int      g_repair_count;
__device__ int      g_repair_tick;
__device__ int      g_gather_done;
__device__ double   g_partials[1024];

__device__ __forceinline__ uint32_t smem_u32(const void* p) {
    uint32_t a;
    asm("{ .reg .u64 t; cvta.to.shared.u64 t, %1; cvt.u32.u64 %0, t; }" : "=r"(a) : "l"(p));
    return a;
}
__device__ __forceinline__ void cp_async16(uint32_t dst, const void* src) {
    asm volatile("cp.async.cg.shared.global [%0], [%1], 16;\n" :: "r"(dst), "l"(src));
}
__device__ __forceinline__ void mma16(float* d,
                                      uint32_t a0, uint32_t a1, uint32_t a2, uint32_t a3,
                                      uint32_t b0, uint32_t b1) {
    asm volatile("mma.sync.aligned.m16n8k16.row.col.f32.f16.f16.f32 "
                 "{%0,%1,%2,%3}, {%4,%5,%6,%7}, {%8,%9}, {%0,%1,%2,%3};"
                 : "+f"(d[0]), "+f"(d[1]), "+f"(d[2]), "+f"(d[3])
                 : "r"(a0), "r"(a1), "r"(a2), "r"(a3), "r"(b0), "r"(b1));
}
__device__ __forceinline__ ULL u64min(ULL a, ULL b) { return a < b ? a : b; }
__device__ __forceinline__ uint32_t pack_h2(float x, float y) {
    __half2 h = __floats2half2_rn(x, y);
    return *(uint32_t*)&h;
}

// ---------------------------------------------------------------------------
// Kernel 0: ||e||^2 (reference rounding), biased norms, half2 emb, counters.
// ---------------------------------------------------------------------------
__global__ void prep_kernel(const float* __restrict__ emb) {
    if (blockIdx.x == 0 && threadIdx.x == 0) {
        g_repair_count = 0; g_repair_tick = 0; g_gather_done = 0;
    }
    int code = blockIdx.x * blockDim.x + threadIdx.x;   // 0..1023
    if (code < K) {
        const float* e = emb + code * C;
        uint32_t* o = g_embh + code * (C / 2);
        float acc = 0.f;
        #pragma unroll
        for (int c = 0; c < C; c++) {
            float v = e[c];
            acc = __fadd_rn(acc, __fmul_rn(v, v));
        }
        #pragma unroll
        for (int kp = 0; kp < C / 2; kp++)
            o[kp] = pack_h2(e[2 * kp], e[2 * kp + 1]);
        g_enorm[code] = acc;
        g_ens[code]   = VAL_BIAS + acc;
    }
}

// ---------------------------------------------------------------------------
// Kernel 1: single-pass fp16 mma score GEMM + fused argmin.
// Score key: val = fma(-2, S, 0.1+en) (zn dropped: row-constant), packed into
// a 32-bit key (valbits & ~0x7FF) | code -> min = lexicographic (val, code).
// Top-2 per thread via IMNMX; rows with quantized gap <= EPS_TIE enqueued
// for exact rescore. Triple-buffered B, ONE syncthreads per chunk. Occ 2.
// ---------------------------------------------------------------------------
__global__ __launch_bounds__(256, 2)
void argmin_kernel(const float* __restrict__ z) {
    extern __shared__ char smem[];
    uint32_t* A2    = (uint32_t*)smem;                 // [128][36] half2
    uint32_t* B2    = (uint32_t*)(smem + B_OFF);       // [3][128][36]
    float*    ens_s = (float*)(smem + ENS_OFF);        // [1024] biased norms
    uint32_t* red1  = (uint32_t*)(smem + RED_OFF);     // [2][128] best key
    uint32_t* red2  = red1 + 256;                      // [2][128] 2nd key
    const uint32_t sb = smem_u32(smem);

    const int tid  = threadIdx.x;
    const int lane = tid & 31;
    const int wid  = tid >> 5;
    const int wm   = wid & 3;       // row band (32 rows)
    const int wn   = wid >> 2;      // code half (64 codes)
    const int arow = lane >> 2;     // 0..7
    const int acol = lane & 3;      // 0..3

    const int n0  = blockIdx.x * TM;
    const int bB  = n0 >> 12;                     // 128 | 4096: no batch crossing
    const int hw0 = n0 & (HW - 1);
    const float* zb = z + (size_t)bB * CHW + hw0; // zb[k*HW + m]

    // --- A tile: z -> half2 pairs A2[m][kp]; full 128 rows x 32 kp ---
    #pragma unroll
    for (int i = 0; i < 16; i++) {
        int f  = tid + 256 * i;                   // 4096 (kp, m) pairs
        int m  = f & 127, kp = f >> 7;
        float v0 = zb[(2 * kp) * HW + m];
        float v1 = zb[(2 * kp + 1) * HW + m];
        A2[m * PW + kp] = pack_h2(v0, v1);
    }
    // exact ||z||^2 per row (reference op order) -> global, for repair only.
    if (tid < TM) {
        float acc = 0.f;
        const float* p = zb + tid;
        #pragma unroll
        for (int c = 0; c < C; c++) {
            float v = p[c * HW];
            acc = __fadd_rn(acc, __fmul_rn(v, v));
        }
        g_zn[n0 + tid] = acc;
    }
    #pragma unroll
    for (int i = 0; i < 4; i++) ens_s[tid + 256 * i] = g_ens[tid + 256 * i];

    // --- cp.async B chunk 0 into buffer 0 ---
    {
        const char* src = (const char*)g_embh;
        #pragma unroll
        for (int i = 0; i < 4; i++) {
            int q = tid + 256 * i;                // 1024 x 16B
            int code = q >> 3, seg = q & 7;
            uint32_t dst = sb + (uint32_t)(B_OFF + code * (PW * 4) + seg * 16);
            cp_async16(dst, src + q * 16);
        }
        asm volatile("cp.async.commit_group;\n");
    }

    // per-thread top-2 32-bit keys per (mi, rh)
    uint32_t k1[2][2], k2[2][2];
    #pragma unroll
    for (int a = 0; a < 2; a++)
        #pragma unroll
        for (int b = 0; b < 2; b++) { k1[a][b] = 0xFFFFFFFFu; k2[a][b] = 0xFFFFFFFFu; }

    for (int c = 0; c < NCH; c++) {
        // prefetch chunk c+1 into buf[(c+1)%3]; safe: its last reader was
        // iter c-2, finished before sync(c-1) which we already passed.
        if (c + 1 < NCH) {
            const char* src = (const char*)(g_embh + (c + 1) * CH * (C / 2));
            const int boff = B_OFF + ((c + 1) % 3) * B_BYTES;
            #pragma unroll
            for (int i = 0; i < 4; i++) {
                int q = tid + 256 * i;
                int code = q >> 3, seg = q & 7;
                uint32_t dst = sb + (uint32_t)(boff + code * (PW * 4) + seg * 16);
                cp_async16(dst, src + q * 16);
            }
            asm volatile("cp.async.commit_group;\n");
            asm volatile("cp.async.wait_group 1;\n");
        } else {
            asm volatile("cp.async.wait_group 0;\n");
        }
        __syncthreads();   // chunk c data visible; all warps past epi(c-1)

        const uint32_t* Aw = A2 + (32 * wm) * PW;
        const uint32_t* Bw = B2 + (c % 3) * (CH * PW) + (64 * wn) * PW;

        float acc[2][8][4];
        #pragma unroll
        for (int mi = 0; mi < 2; mi++)
            #pragma unroll
            for (int ni = 0; ni < 8; ni++)
                #pragma unroll
                for (int r = 0; r < 4; r++) acc[mi][ni][r] = 0.f;

        #pragma unroll
        for (int ks = 0; ks < 4; ks++) {          // 4 k-steps of 16
            uint32_t af[2][4];
            #pragma unroll
            for (int mi = 0; mi < 2; mi++) {
                const uint32_t* Ap = Aw + (16 * mi + arow) * PW + ks * 8 + acol;
                af[mi][0] = Ap[0];
                af[mi][1] = Ap[8 * PW];
                af[mi][2] = Ap[4];
                af[mi][3] = Ap[8 * PW + 4];
            }
            uint32_t bf[8][2];
            #pragma unroll
            for (int ni = 0; ni < 8; ni++) {
                const uint32_t* Bp = Bw + (8 * ni + arow) * PW + ks * 8 + acol;
                bf[ni][0] = Bp[0];
                bf[ni][1] = Bp[4];
            }
            #pragma unroll
            for (int mi = 0; mi < 2; mi++)
                #pragma unroll
                for (int ni = 0; ni < 8; ni++)
                    mma16(acc[mi][ni],
                          af[mi][0], af[mi][1], af[mi][2], af[mi][3],
                          bf[ni][0], bf[ni][1]);
        }

        // epilogue: biased scores -> packed 32-bit keys -> per-thread top-2
        const int code0 = c * CH + 64 * wn;
        #pragma unroll
        for (int ni = 0; ni < 8; ni++) {
            float2 ens2 = *(const float2*)(ens_s + code0 + 8 * ni + 2 * acol);
            const uint32_t cbase = (uint32_t)(code0 + 8 * ni + 2 * acol);
            #pragma unroll
            for (int mi = 0; mi < 2; mi++)
                #pragma unroll
                for (int rh = 0; rh < 2; rh++) {
                    float v0 = __fmaf_rn(-2.0f, acc[mi][ni][2 * rh + 0], ens2.x);
                    float v1 = __fmaf_rn(-2.0f, acc[mi][ni][2 * rh + 1], ens2.y);
                    uint32_t key0 = (__float_as_uint(v0) & 0xFFFFF800u) | cbase;
                    uint32_t key1 = (__float_as_uint(v1) & 0xFFFFF800u) | (cbase + 1);
                    uint32_t lo, hi;
                    lo = umin(k1[mi][rh], key0); hi = umax(k1[mi][rh], key0);
                    k1[mi][rh] = lo; k2[mi][rh] = umin(k2[mi][rh], hi);
                    lo = umin(k1[mi][rh], key1); hi = umax(k1[mi][rh], key1);
                    k1[mi][rh] = lo; k2[mi][rh] = umin(k2[mi][rh], hi);
                }
        }
        // no bottom sync: triple buffer guarantees no WAR on B
    }

    // reduce top-2 across the 4 acol lanes sharing each row
    #pragma unroll
    for (int mi = 0; mi < 2; mi++)
        #pragma unroll
        for (int rh = 0; rh < 2; rh++) {
            uint32_t a1 = k1[mi][rh], a2 = k2[mi][rh];
            #pragma unroll
            for (int m = 1; m <= 2; m <<= 1) {
                uint32_t o1 = __shfl_xor_sync(0xffffffffu, a1, m);
                uint32_t o2 = __shfl_xor_sync(0xffffffffu, a2, m);
                uint32_t lo = umin(a1, o1), hi = umax(a1, o1);
                a1 = lo;
                a2 = umin(umin(a2, o2), hi);
            }
            if (acol == 0) {
                int row = 32 * wm + 16 * mi + arow + 8 * rh;
                red1[wn * TM + row] = a1;
                red2[wn * TM + row] = a2;
            }
        }
    __syncthreads();

    // final per-row merge across the two code-halves + ambiguity flagging
    if (tid < TM) {
        uint32_t a1 = red1[tid], b1 = red1[TM + tid];
        uint32_t a2 = red2[tid], b2 = red2[TM + tid];
        uint32_t t1 = umin(a1, b1);
        uint32_t hi = umax(a1, b1);
        uint32_t t2 = umin(umin(a2, b2), hi);

        g_idx[n0 + tid] = (int)(t1 & 0x7FFu);     // provisional winner
        float v1f = __uint_as_float(t1 & 0xFFFFF800u);
        float v2f = __uint_as_float(t2 & 0xFFFFF800u);
        if (v2f - v1f <= EPS_TIE) {
            int pos = atomicAdd(&g_repair_count, 1);
            g_repair_rows[pos] = n0 + tid;
        }
    }
}

// ---------------------------------------------------------------------------
// Kernel 1b: exact full rescore of flagged rows (all 1024 codes), exact
// fp32 fmaf dot; min by lexicographic (d, code). (Unchanged; R9-proven.)
// ---------------------------------------------------------------------------
__global__ __launch_bounds__(256) void repair_kernel(const float* __restrict__ z,
                                                     const float* __restrict__ emb) {
    __shared__ float es[128 * 65];
    __shared__ float ze[16 * 66];
    __shared__ float zn_sh[16];
    __shared__ int   rows_sh[16];
    __shared__ int   s_base;

    const int tid = threadIdx.x;
    const int r   = tid >> 4;
    const int cc  = tid & 15;

    for (;;) {
        if (tid == 0) s_base = atomicAdd(&g_repair_tick, 16);
        __syncthreads();
        const int base = s_base;
        const int cnt  = g_repair_count;
        if (base >= cnt) break;
        const int nrows = min(16, cnt - base);

        if (tid < nrows) {
            int n = g_repair_rows[base + tid];
            rows_sh[tid] = n;
            zn_sh[tid]   = g_zn[n];
        }
        __syncthreads();
        #pragma unroll
        for (int i = 0; i < 4; i++) {
            int e2 = tid + 256 * i;
            int rr = e2 >> 6, k = e2 & 63;
            if (rr < nrows) {
                int n = rows_sh[rr], b = n >> 12, hw = n & (HW - 1);
                ze[rr * 66 + k] = z[(size_t)b * CHW + k * HW + hw];
            }
        }
        __syncthreads();

        ULL best = ~0ULL;
        for (int ch = 0; ch < 8; ch++) {
            #pragma unroll
            for (int i = 0; i < 32; i++) {
                int f = tid + 256 * i;
                int code = f >> 6, k = f & 63;
                es[code * 65 + k] = emb[ch * 8192 + f];
            }
            __syncthreads();
            if (r < nrows) {
                float S[8];
                #pragma unroll
                for (int j = 0; j < 8; j++) S[j] = 0.f;
                #pragma unroll 8
                for (int k = 0; k < 64; k++) {
                    float zk = ze[r * 66 + k];
                    #pragma unroll
                    for (int j = 0; j < 8; j++)
                        S[j] = __fmaf_rn(zk, es[(cc + 16 * j) * 65 + k], S[j]);
                }
                float zn = zn_sh[r];
                #pragma unroll
                for (int j = 0; j < 8; j++) {
                    int code = ch * 128 + cc + 16 * j;
                    float d = __fadd_rn(__fadd_rn(zn, __fmul_rn(-2.0f, S[j])), g_enorm[code]);
                    ULL key = ((ULL)__float_as_uint(d) << 32) | (unsigned)code;
                    if (key < best) best = key;
                }
            }
            __syncthreads();
        }
        #pragma unroll
        for (int m = 1; m < 16; m <<= 1) {
            ULL o = __shfl_xor_sync(0xffffffffu, best, m);
            best = u64min(best, o);
        }
        if (cc == 0 && r < nrows) g_idx[rows_sh[r]] = (int)(best & 0xffffffffULL);
        __syncthreads();
    }
}

// ---------------------------------------------------------------------------
// Kernel 2: gather + straight-through output + loss (fused last-block finish).
// 4 threads/row x 16 channels; e rows loaded as float4 (4x fewer sectors).
// ---------------------------------------------------------------------------
__global__ __launch_bounds__(256) void gather_kernel(const float* __restrict__ z,
                                                     const float* __restrict__ emb,
                                                     float* __restrict__ out) {
    const int tid = threadIdx.x;
    const int m   = tid & 63;
    const int cg  = tid >> 6;          // channel group 0..3
    const int n   = blockIdx.x * 64 + m;
    const int b   = n >> 12, hw = n & (HW - 1);
    const float* zp = z + (size_t)b * CHW + hw;
    float* op = out + (size_t)b * CHW + hw;
    const int idx = g_idx[n];
    const float4* e4 = (const float4*)(emb + idx * C + cg * 16);

    double s = 0.0;
    #pragma unroll
    for (int j = 0; j < 4; j++) {
        float4 q4 = __ldg(e4 + j);
        float qv[4] = {q4.x, q4.y, q4.z, q4.w};
        #pragma unroll
        for (int t = 0; t < 4; t++) {
            int c = cg * 16 + 4 * j + t;
            float zv   = zp[c * HW];
            float diff = __fadd_rn(qv[t], -zv);
            float qst  = __fadd_rn(zv, diff);
            op[c * HW] = qst;
            s += (double)__fmul_rn(diff, diff);
        }
    }

    __shared__ double sd[256];
    __shared__ bool s_last;
    sd[tid] = s;
    __syncthreads();
    for (int st = 128; st > 0; st >>= 1) {
        if (tid < st) sd[tid] += sd[tid + st];
        __syncthreads();
    }
    if (tid == 0) {
        g_partials[blockIdx.x] = sd[0];
        __threadfence();
        int t = atomicAdd(&g_gather_done, 1);
        s_last = (t == (int)gridDim.x - 1);
    }
    __syncthreads();

    // last block reduces all partials deterministically (fixed array order)
    if (s_last) {
        double s2 = 0.0;
        #pragma unroll
        for (int i = 0; i < 4; i++) s2 += g_partials[tid + 256 * i];
        sd[tid] = s2;
        __syncthreads();
        for (int st = 128; st > 0; st >>= 1) {
            if (tid < st) sd[tid] += sd[tid + st];
            __syncthreads();
        }
        if (tid == 0) {
            float mm = (float)(sd[0] / (double)((size_t)N * C));
            out[(size_t)N * C] = __fadd_rn(mm, 0.25f * mm);
        }
    }
}

// ---------------------------------------------------------------------------
extern "C" void kernel_launch(void* const* d_in, const int* in_sizes, int n_in,
                              void* d_out, int out_size) {
    const float* z   = (const float*)d_in[0];   // [16,64,64,64]
    const float* emb = (const float*)d_in[1];   // [1024,64]
    float* out = (float*)d_out;                 // 4194304 q_st + 1 loss

    cudaFuncSetAttribute(argmin_kernel,
                         cudaFuncAttributeMaxDynamicSharedMemorySize, SMEM_BYTES);

    prep_kernel  <<< 4, 256 >>>(emb);
    argmin_kernel<<< N / TM, 256, SMEM_BYTES >>>(z);
    repair_kernel<<< 128, 256 >>>(z, emb);
    gather_kernel<<< N / 64, 256 >>>(z, emb, out);
}